// round 15
// baseline (speedup 1.0000x reference)
#include <cuda_runtime.h>
#include <cuda_fp16.h>
#include <cstdint>

typedef unsigned int uint;

#define C_IN    64
#define INHW    224
#define NQ      (INHW*INHW)        // 50176 input pixels
#define QMAX    (NQ-1)
#define C_OUT   128
#define OHW     222
#define NPIX    (OHW*OHW)          // 49284
#define NTAP    9
#define TILE_N  96
#define NTILES  ((NPIX + TILE_N - 1)/TILE_N)   // 514
#define BROWS   100                // B smem rows per kr (96 + ks 2 + rowcross 2)

#define XBLK    (NQ/256)           // 196 transpose blocks
#define WBLK    36

// x transposed to [q][ic] fp16 (6.4 MB)
__device__ __align__(16) __half g_xf[NQ * C_IN];
// w as [tap][oc][ic] fp16 with XOR-swizzle pre-baked per oc row (verbatim bulk copy)
__device__ __align__(16) __half g_wf[NTAP * C_OUT * C_IN];

// ---------------- combined prep kernel (conflict-free transpose) ----------------
__global__ void prep_kernel(const float* __restrict__ x, const float* __restrict__ w)
{
    const int tid = threadIdx.x;
    if (blockIdx.x < XBLK) {
        // row stride 33 words: bank = (tid + c2) % 32 -> conflict-free both phases
        __shared__ uint sm32[256 * 33];          // 33792 B
        const int q0 = blockIdx.x * 256;
        #pragma unroll 8
        for (int c2 = 0; c2 < 32; ++c2) {
            float v0 = x[(size_t)(2 * c2 + 0) * NQ + q0 + tid];
            float v1 = x[(size_t)(2 * c2 + 1) * NQ + q0 + tid];
            __half2 h = __floats2half2_rn(v0, v1);
            sm32[tid * 33 + c2] = *(const uint*)&h;
        }
        __syncthreads();
        #pragma unroll
        for (int it = 0; it < 8; ++it) {
            const int i = tid + it * 256;        // 256 q x 8 granules
            const int q = i >> 3;
            const int g = i & 7;
            uint4 v;
            v.x = sm32[q * 33 + 4 * g + 0];
            v.y = sm32[q * 33 + 4 * g + 1];
            v.z = sm32[q * 33 + 4 * g + 2];
            v.w = sm32[q * 33 + 4 * g + 3];
            *(uint4*)&g_xf[(size_t)(q0 + q) * 64 + g * 8] = v;
        }
    } else {
        const int base = (blockIdx.x - XBLK) * 2048 + tid * 8;
        #pragma unroll
        for (int k = 0; k < 8; ++k) {
            const int i = base + k;
            if (i < NTAP * C_OUT * C_IN) {
                const int ic = i & 63;
                const int r  = i >> 6;
                const int oc = r & 127;
                const int t  = r >> 7;
                float v = w[(size_t)(oc * C_IN + ic) * NTAP + t];
                const int jp = (ic >> 3) ^ (oc & 7);
                g_wf[(size_t)t * (C_OUT * C_IN) + oc * C_IN + jp * 8 + (ic & 7)] =
                    __float2half(v);
            }
        }
    }
}

// ---------------- PTX helpers ----------------
__device__ __forceinline__ uint smem_u32(const void* p) {
    uint a;
    asm("{ .reg .u64 t; cvta.to.shared.u64 t, %1; cvt.u32.u64 %0, t; }"
        : "=r"(a) : "l"(p));
    return a;
}
__device__ __forceinline__ void cpa16(uint d, const void* s) {
    asm volatile("cp.async.ca.shared.global [%0], [%1], 16;" :: "r"(d), "l"(s) : "memory");
}
__device__ __forceinline__ void cpa_commit() {
    asm volatile("cp.async.commit_group;" ::: "memory");
}
__device__ __forceinline__ void cpa_wait2() {
    asm volatile("cp.async.wait_group 2;" ::: "memory");
}
__device__ __forceinline__ void cpa_wait1() {
    asm volatile("cp.async.wait_group 1;" ::: "memory");
}
__device__ __forceinline__ void cpa_wait0() {
    asm volatile("cp.async.wait_group 0;" ::: "memory");
}
__device__ __forceinline__ void mbar_init(uint a, uint cnt) {
    asm volatile("mbarrier.init.shared.b64 [%0], %1;" :: "r"(a), "r"(cnt) : "memory");
}
__device__ __forceinline__ void mbar_expect_tx(uint a, uint bytes) {
    asm volatile("mbarrier.arrive.expect_tx.shared.b64 _, [%0], %1;"
                 :: "r"(a), "r"(bytes) : "memory");
}
__device__ __forceinline__ void bulk_g2s(uint dst, const void* src, uint bytes, uint mbar) {
    asm volatile("cp.async.bulk.shared::cluster.global.mbarrier::complete_tx::bytes "
                 "[%0], [%1], %2, [%3];"
                 :: "r"(dst), "l"(src), "r"(bytes), "r"(mbar) : "memory");
}
__device__ __forceinline__ void fence_async() {
    asm volatile("fence.proxy.async.shared::cta;" ::: "memory");
}
__device__ __forceinline__ void mbar_wait(uint a, uint parity) {
    uint done;
    asm volatile("{\n\t.reg .pred p;\n\t"
                 "mbarrier.try_wait.parity.acquire.cta.shared::cta.b64 p, [%1], %2;\n\t"
                 "selp.b32 %0, 1, 0, p;\n\t}"
                 : "=r"(done) : "r"(a), "r"(parity) : "memory");
    if (!done) {
        asm volatile("{\n\t.reg .pred P1;\n\t"
                     "WL_%=:\n\t"
                     "mbarrier.try_wait.parity.acquire.cta.shared::cta.b64 P1, [%0], %1, 0x989680;\n\t"
                     "@P1 bra.uni WD_%=;\n\t"
                     "bra.uni WL_%=;\n\t"
                     "WD_%=:\n\t}"
                     :: "r"(a), "r"(parity) : "memory");
    }
}
__device__ __forceinline__ void ldsm4(uint& r0, uint& r1, uint& r2, uint& r3, uint a) {
    asm volatile("ldmatrix.sync.aligned.m8n8.x4.shared.b16 {%0,%1,%2,%3}, [%4];"
                 : "=r"(r0), "=r"(r1), "=r"(r2), "=r"(r3) : "r"(a));
}
__device__ __forceinline__ void mma_f16(float* c, const uint* a, uint b0, uint b1) {
    asm volatile("mma.sync.aligned.m16n8k16.row.col.f32.f16.f16.f32 "
                 "{%0,%1,%2,%3}, {%4,%5,%6,%7}, {%8,%9}, {%0,%1,%2,%3};"
                 : "+f"(c[0]), "+f"(c[1]), "+f"(c[2]), "+f"(c[3])
                 : "r"(a[0]), "r"(a[1]), "r"(a[2]), "r"(a[3]), "r"(b0), "r"(b1));
}

// ---------------- SMEM layout: 3x A bufs, 3x B bufs ----------------
#define SM_MBAR   0
#define SM_A0     1024
#define A_BYTES   16384
#define SM_B0     (1024 + 3*A_BYTES)       // 50176
#define B_BYTES   (BROWS*128)              // 12800
#define SMEM_SZ   (SM_B0 + 3*B_BYTES)      // 88576 -> 2 CTAs/SM

// ---------------- main kernel ----------------
__global__ __launch_bounds__(256, 2)
void conv_hmma_fp16_kernel(float* __restrict__ out)
{
    extern __shared__ char smem[];
    const uint sb  = smem_u32(smem);
    const int tid  = threadIdx.x;
    const int wid  = tid >> 5;
    const int lid  = tid & 31;
    const int wm   = wid & 3;          // m-quarter (32 rows)
    const int wn   = wid >> 2;         // n-half (48 cols)

    const int p0  = blockIdx.x * TILE_N;
    const int oh0 = p0 / OHW;
    const int ow0 = p0 - oh0 * OHW;

    if (tid == 0) {
        mbar_init(sb + SM_MBAR +  0, 1);
        mbar_init(sb + SM_MBAR + 16, 1);
        mbar_init(sb + SM_MBAR + 32, 1);
        fence_async();
    }
    __syncthreads();

    const int  rA = wm * 32 + (lid & 15);
    const int  sA = lid >> 4;
    const int  cA = rA & 7;
    const int  rB = wn * 48 + ((lid >> 4) << 3) + (lid & 7);
    const int  sB = (lid >> 3) & 1;
    // base rows for the 3 B-ldsm4s (n-offsets 0,16,32), with output-row-cross fix
    int rowQ[3];
    #pragma unroll
    for (int q = 0; q < 3; ++q) {
        const int n = rB + 16 * q;
        rowQ[q] = n + ((ow0 + n >= OHW) ? 2 : 0);
    }

    auto stage_B = [&](int kr) {
        const uint bbuf = sb + SM_B0 + (uint)kr * B_BYTES;
        const int  qb   = (oh0 + kr) * INHW + ow0;
        #pragma unroll 1
        for (int idx = tid; idx < BROWS * 8; idx += 256) {
            const int r = idx >> 3;
            const int j = idx & 7;
            const int q = (qb + r) > QMAX ? QMAX : (qb + r);
            cpa16(bbuf + r * 128 + (((j ^ (r & 7))) << 4),
                  (const char*)g_xf + (size_t)q * 128 + j * 16);
        }
    };
    auto stage_A = [&](int t) {
        if (tid == 0) {
            const int  b  = t % 3;
            const uint mb = sb + SM_MBAR + (uint)b * 16;
            mbar_expect_tx(mb, A_BYTES);
            bulk_g2s(sb + SM_A0 + (uint)b * A_BYTES,
                     (const char*)g_wf + (size_t)t * A_BYTES, A_BYTES, mb);
        }
    };

    float acc[48];
    #pragma unroll
    for (int i = 0; i < 48; ++i) acc[i] = 0.f;

    stage_B(0); cpa_commit();
    stage_B(1); cpa_commit();
    stage_B(2); cpa_commit();
    stage_A(0);
    stage_A(1);

    #pragma unroll 1
    for (int t = 0; t < NTAP; ++t) {
        const int kr = t / 3;
        if      (t == 0) cpa_wait2();
        else if (t == 3) cpa_wait1();
        else if (t == 6) cpa_wait0();

        const int b = t % 3;
        mbar_wait(sb + SM_MBAR + (uint)b * 16, (t / 3) & 1);
        __syncthreads();
        if (t + 2 < NTAP) stage_A(t + 2);

        const uint abuf = sb + SM_A0 + (uint)b * A_BYTES;
        const uint bbuf = sb + SM_B0 + (uint)kr * B_BYTES;
        const uint aRow = abuf + (uint)rA * 128;
        const int  ks   = t - kr * 3;

        #pragma unroll
        for (int k = 0; k < 4; ++k) {
            uint bf[12];
            #pragma unroll
            for (int q = 0; q < 3; ++q) {
                const int  row  = rowQ[q] + ks;
                const uint addr = bbuf + (uint)row * 128
                                + (uint)(((2 * k + sB) ^ (row & 7)) << 4);
                ldsm4(bf[q*4+0], bf[q*4+1], bf[q*4+2], bf[q*4+3], addr);
            }
            #pragma unroll
            for (int i = 0; i < 2; ++i) {
                uint a[4];
                ldsm4(a[0], a[1], a[2], a[3],
                      aRow + (uint)i * 2048 + (uint)(((2 * k + sA) ^ cA) << 4));
                #pragma unroll
                for (int j = 0; j < 6; ++j)
                    mma_f16(&acc[(i * 6 + j) * 4], a, bf[j*2], bf[j*2+1]);
            }
        }
    }

    // ---- epilogue ----
    const int ml = wm * 32 + (lid >> 2);
    const int nl = wn * 48 + (lid & 3) * 2;
    #pragma unroll
    for (int i = 0; i < 2; ++i) {
        #pragma unroll
        for (int j = 0; j < 6; ++j) {
            const float* c = &acc[(i * 6 + j) * 4];
            const int n = nl + j * 8;
            const int p = p0 + n;
            if (p < NPIX) {                       // p even, NPIX even -> pair valid
                const int m0 = ml + i * 16;
                *(float2*)(out + (size_t)m0 * NPIX + p)       = make_float2(c[0], c[1]);
                *(float2*)(out + (size_t)(m0 + 8) * NPIX + p) = make_float2(c[2], c[3]);
            }
        }
    }
}

// ---------------- launch ----------------
extern "C" void kernel_launch(void* const* d_in, const int* in_sizes, int n_in,
                              void* d_out, int out_size)
{
    const float* x = (const float*)d_in[0];   // (64, 224, 224) f32
    const float* w = (const float*)d_in[1];   // (128, 64, 3, 3) f32
    float* out = (float*)d_out;               // (128, 222, 222) f32

    cudaFuncSetAttribute(conv_hmma_fp16_kernel,
                         cudaFuncAttributeMaxDynamicSharedMemorySize, SMEM_SZ);

    prep_kernel<<<XBLK + WBLK, 256>>>(x, w);
    conv_hmma_fp16_kernel<<<NTILES, 256, SMEM_SZ>>>(out);
}

// round 17
// speedup vs baseline: 1.0601x; 1.0601x over previous
#include <cuda_runtime.h>
#include <cuda_fp16.h>
#include <cstdint>

typedef unsigned int uint;

#define C_IN    64
#define INHW    224
#define NQ      (INHW*INHW)        // 50176 input pixels
#define QMAX    (NQ-1)
#define C_OUT   128
#define OHW     222
#define NPIX    (OHW*OHW)          // 49284
#define NTAP    9
#define TILE_N  128
#define NTILES  ((NPIX + TILE_N - 1)/TILE_N)   // 386
#define BROWS   132                // B smem rows per kr (128 + ks 2 + rowcross 2)

#define XQB     224                // q per transpose block
#define XBLK    (NQ/XQB)           // 224 blocks
#define WBLK    36
#define PREP_SMEM (C_IN * XQB * 4) // 57344 B staged f32

// x transposed to [q][ic] fp16 (6.4 MB)
__device__ __align__(16) __half g_xf[NQ * C_IN];
// w as [tap][oc][ic] fp16 with XOR-swizzle pre-baked per oc row (verbatim bulk copy)
__device__ __align__(16) __half g_wf[NTAP * C_OUT * C_IN];

// ---------------- PTX helpers ----------------
__device__ __forceinline__ uint smem_u32(const void* p) {
    uint a;
    asm("{ .reg .u64 t; cvta.to.shared.u64 t, %1; cvt.u32.u64 %0, t; }"
        : "=r"(a) : "l"(p));
    return a;
}
__device__ __forceinline__ void cpa16(uint d, const void* s) {
    asm volatile("cp.async.ca.shared.global [%0], [%1], 16;" :: "r"(d), "l"(s) : "memory");
}
__device__ __forceinline__ void cpa_commit() {
    asm volatile("cp.async.commit_group;" ::: "memory");
}
__device__ __forceinline__ void cpa_wait2() {
    asm volatile("cp.async.wait_group 2;" ::: "memory");
}
__device__ __forceinline__ void cpa_wait1() {
    asm volatile("cp.async.wait_group 1;" ::: "memory");
}
__device__ __forceinline__ void cpa_wait0() {
    asm volatile("cp.async.wait_group 0;" ::: "memory");
}
__device__ __forceinline__ void mbar_init(uint a, uint cnt) {
    asm volatile("mbarrier.init.shared.b64 [%0], %1;" :: "r"(a), "r"(cnt) : "memory");
}
__device__ __forceinline__ void mbar_expect_tx(uint a, uint bytes) {
    asm volatile("mbarrier.arrive.expect_tx.shared.b64 _, [%0], %1;"
                 :: "r"(a), "r"(bytes) : "memory");
}
__device__ __forceinline__ void bulk_g2s(uint dst, const void* src, uint bytes, uint mbar) {
    asm volatile("cp.async.bulk.shared::cluster.global.mbarrier::complete_tx::bytes "
                 "[%0], [%1], %2, [%3];"
                 :: "r"(dst), "l"(src), "r"(bytes), "r"(mbar) : "memory");
}
__device__ __forceinline__ void fence_async() {
    asm volatile("fence.proxy.async.shared::cta;" ::: "memory");
}
__device__ __forceinline__ void mbar_wait(uint a, uint parity) {
    uint done;
    asm volatile("{\n\t.reg .pred p;\n\t"
                 "mbarrier.try_wait.parity.acquire.cta.shared::cta.b64 p, [%1], %2;\n\t"
                 "selp.b32 %0, 1, 0, p;\n\t}"
                 : "=r"(done) : "r"(a), "r"(parity) : "memory");
    if (!done) {
        asm volatile("{\n\t.reg .pred P1;\n\t"
                     "WL_%=:\n\t"
                     "mbarrier.try_wait.parity.acquire.cta.shared::cta.b64 P1, [%0], %1, 0x989680;\n\t"
                     "@P1 bra.uni WD_%=;\n\t"
                     "bra.uni WL_%=;\n\t"
                     "WD_%=:\n\t}"
                     :: "r"(a), "r"(parity) : "memory");
    }
}
__device__ __forceinline__ void ldsm4(uint& r0, uint& r1, uint& r2, uint& r3, uint a) {
    asm volatile("ldmatrix.sync.aligned.m8n8.x4.shared.b16 {%0,%1,%2,%3}, [%4];"
                 : "=r"(r0), "=r"(r1), "=r"(r2), "=r"(r3) : "r"(a));
}
__device__ __forceinline__ void mma_f16(float* c, const uint* a, uint b0, uint b1) {
    asm volatile("mma.sync.aligned.m16n8k16.row.col.f32.f16.f16.f32 "
                 "{%0,%1,%2,%3}, {%4,%5,%6,%7}, {%8,%9}, {%0,%1,%2,%3};"
                 : "+f"(c[0]), "+f"(c[1]), "+f"(c[2]), "+f"(c[3])
                 : "r"(a[0]), "r"(a[1]), "r"(a[2]), "r"(a[3]), "r"(b0), "r"(b1));
}

// ---------------- combined prep kernel ----------------
// blocks [0, XBLK): cp.async-staged conflict-free transpose x -> g_xf
// blocks [XBLK, XBLK+WBLK): weight conversion -> g_wf
__global__ void prep_kernel(const float* __restrict__ x, const float* __restrict__ w)
{
    extern __shared__ float smf[];               // [c=64][224 q f32], row 896B
    const int tid = threadIdx.x;
    if (blockIdx.x < XBLK) {
        const int  q0 = blockIdx.x * XQB;
        const uint sb = smem_u32(smf);
        // phase 1: async-stage 64 channel rows, granule-permuted within each row
        #pragma unroll
        for (int it = 0; it < 14; ++it) {
            const int idx = tid + it * 256;       // 3584 granules
            const int r   = idx / 56;             // channel
            const int col = idx - r * 56;         // 16B granule in row
            const int f   = (r & 7) ^ ((r >> 3) & 7);
            const int cp  = (col & ~7) | ((col & 7) ^ f);
            cpa16(sb + (uint)(r * 896 + cp * 16),
                  x + (size_t)r * NQ + q0 + col * 4);
        }
        cpa_commit();
        cpa_wait0();
        __syncthreads();
        // phase 2: conflict-free gather + convert + coalesced STG.128
        const int l    = tid & 31;
        const int wq   = l & 3;                   // q sub-index
        const int g    = (l >> 2) & 7;            // output ic-granule
        #pragma unroll
        for (int it = 0; it < 7; ++it) {
            const int Q  = ((tid + it * 256) >> 5) * 4;   // 4-aligned q base (0..220)
            const int q  = Q + wq;
            const int gq = q >> 2;                 // source granule of q
            __align__(16) __half h[8];
            #pragma unroll
            for (int j = 0; j < 8; ++j) {
                const int c  = 8 * g + j;
                const int f  = j ^ g;              // (c&7)^(c>>3) for c=8g+j
                const int cp = (gq & ~7) | ((gq & 7) ^ f);
                h[j] = __float2half(smf[c * 224 + cp * 4 + (q & 3)]);
            }
            *(uint4*)&g_xf[(size_t)(q0 + q) * 64 + g * 8] = *(const uint4*)h;
        }
    } else {
        const int base = (blockIdx.x - XBLK) * 2048 + tid * 8;
        #pragma unroll
        for (int k = 0; k < 8; ++k) {
            const int i = base + k;
            if (i < NTAP * C_OUT * C_IN) {
                const int ic = i & 63;
                const int r  = i >> 6;
                const int oc = r & 127;
                const int t  = r >> 7;
                float v = w[(size_t)(oc * C_IN + ic) * NTAP + t];
                const int jp = (ic >> 3) ^ (oc & 7);
                g_wf[(size_t)t * (C_OUT * C_IN) + oc * C_IN + jp * 8 + (ic & 7)] =
                    __float2half(v);
            }
        }
    }
}

// ---------------- SMEM layout (main): 3x A bufs, 3x B bufs ----------------
#define SM_MBAR   0
#define SM_A0     1024
#define A_BYTES   16384
#define SM_B0     (1024 + 3*A_BYTES)       // 50176
#define B_BYTES   (BROWS*128)              // 16896
#define SMEM_SZ   (SM_B0 + 3*B_BYTES)      // 100864 -> 2 CTAs/SM

// ---------------- main kernel (identical to R13 best) ----------------
__global__ __launch_bounds__(256, 2)
void conv_hmma_fp16_kernel(float* __restrict__ out)
{
    extern __shared__ char smem[];
    const uint sb  = smem_u32(smem);
    const int tid  = threadIdx.x;
    const int wid  = tid >> 5;
    const int lid  = tid & 31;
    const int wm   = wid & 1;          // m-half (64 rows)
    const int wn   = wid >> 1;         // n-quarter (32 cols)

    const int p0  = blockIdx.x * TILE_N;
    const int oh0 = p0 / OHW;
    const int ow0 = p0 - oh0 * OHW;

    if (tid == 0) {
        mbar_init(sb + SM_MBAR +  0, 1);
        mbar_init(sb + SM_MBAR + 16, 1);
        mbar_init(sb + SM_MBAR + 32, 1);
        fence_async();
    }
    __syncthreads();

    const int  rA = wm * 64 + (lid & 15);
    const int  sA = lid >> 4;
    const int  cA = rA & 7;
    const int  rB = wn * 32 + ((lid >> 4) << 3) + (lid & 7);
    const int  sB = (lid >> 3) & 1;
    int rowQ[2];
    #pragma unroll
    for (int q = 0; q < 2; ++q) {
        const int n = rB + 16 * q;
        rowQ[q] = n + ((ow0 + n >= OHW) ? 2 : 0);
    }

    auto stage_B = [&](int kr) {
        const uint bbuf = sb + SM_B0 + (uint)kr * B_BYTES;
        const int  qb   = (oh0 + kr) * INHW + ow0;
        #pragma unroll 1
        for (int idx = tid; idx < BROWS * 8; idx += 256) {
            const int r = idx >> 3;
            const int j = idx & 7;
            const int q = (qb + r) > QMAX ? QMAX : (qb + r);
            cpa16(bbuf + r * 128 + (((j ^ (r & 7))) << 4),
                  (const char*)g_xf + (size_t)q * 128 + j * 16);
        }
    };
    auto stage_A = [&](int t) {
        if (tid == 0) {
            const int  b  = t % 3;
            const uint mb = sb + SM_MBAR + (uint)b * 16;
            mbar_expect_tx(mb, A_BYTES);
            bulk_g2s(sb + SM_A0 + (uint)b * A_BYTES,
                     (const char*)g_wf + (size_t)t * A_BYTES, A_BYTES, mb);
        }
    };

    float acc[64];
    #pragma unroll
    for (int i = 0; i < 64; ++i) acc[i] = 0.f;

    stage_B(0); cpa_commit();
    stage_B(1); cpa_commit();
    stage_B(2); cpa_commit();
    stage_A(0);
    stage_A(1);

    #pragma unroll 1
    for (int t = 0; t < NTAP; ++t) {
        const int kr = t / 3;
        if      (t == 0) cpa_wait2();
        else if (t == 3) cpa_wait1();
        else if (t == 6) cpa_wait0();

        const int b = t % 3;
        mbar_wait(sb + SM_MBAR + (uint)b * 16, (t / 3) & 1);
        __syncthreads();
        if (t + 2 < NTAP) stage_A(t + 2);

        const uint abuf = sb + SM_A0 + (uint)b * A_BYTES;
        const uint bbuf = sb + SM_B0 + (uint)kr * B_BYTES;
        const uint aRow = abuf + (uint)rA * 128;
        const int  ks   = t - kr * 3;

        #pragma unroll
        for (int k = 0; k < 4; ++k) {
            uint bf[8];
            #pragma unroll
            for (int q = 0; q < 2; ++q) {
                const int  row  = rowQ[q] + ks;
                const uint addr = bbuf + (uint)row * 128
                                + (uint)(((2 * k + sB) ^ (row & 7)) << 4);
                ldsm4(bf[q*4+0], bf[q*4+1], bf[q*4+2], bf[q*4+3], addr);
            }
            #pragma unroll
            for (int i = 0; i < 4; ++i) {
                uint a[4];
                ldsm4(a[0], a[1], a[2], a[3],
                      aRow + (uint)i * 2048 + (uint)(((2 * k + sA) ^ cA) << 4));
                #pragma unroll
                for (int j = 0; j < 4; ++j)
                    mma_f16(&acc[(i * 4 + j) * 4], a, bf[j*2], bf[j*2+1]);
            }
        }
    }

    const int ml = wm * 64 + (lid >> 2);
    const int nl = wn * 32 + (lid & 3) * 2;
    #pragma unroll
    for (int i = 0; i < 4; ++i) {
        #pragma unroll
        for (int j = 0; j < 4; ++j) {
            const float* c = &acc[(i * 4 + j) * 4];
            const int n = nl + j * 8;
            const int p = p0 + n;
            if (p < NPIX) {
                const int m0 = ml + i * 16;
                *(float2*)(out + (size_t)m0 * NPIX + p)       = make_float2(c[0], c[1]);
                *(float2*)(out + (size_t)(m0 + 8) * NPIX + p) = make_float2(c[2], c[3]);
            }
        }
    }
}

// ---------------- launch ----------------
extern "C" void kernel_launch(void* const* d_in, const int* in_sizes, int n_in,
                              void* d_out, int out_size)
{
    const float* x = (const float*)d_in[0];   // (64, 224, 224) f32
    const float* w = (const float*)d_in[1];   // (128, 64, 3, 3) f32
    float* out = (float*)d_out;               // (128, 222, 222) f32

    cudaFuncSetAttribute(prep_kernel,
                         cudaFuncAttributeMaxDynamicSharedMemorySize, PREP_SMEM);
    cudaFuncSetAttribute(conv_hmma_fp16_kernel,
                         cudaFuncAttributeMaxDynamicSharedMemorySize, SMEM_SZ);

    prep_kernel<<<XBLK + WBLK, 256, PREP_SMEM>>>(x, w);
    conv_hmma_fp16_kernel<<<NTILES, 256, SMEM_SZ>>>(out);
}